// round 1
// baseline (speedup 1.0000x reference)
#include <cuda_runtime.h>

// Problem constants
#define W_DIM 512
#define H_DIM 512
#define B_DIM 8
#define C_DIM 32
#define NBLK  128           // 8 batches * 16 row-tiles of 32 rows
#define NTHR  256

// Scratch: transposed input/output in (W, B, H, C) layout, C contiguous.
__device__ float    g_Xt[W_DIM * B_DIM * H_DIM * C_DIM];   // 256 MB
__device__ float    g_Yt[W_DIM * B_DIM * H_DIM * C_DIM];   // 256 MB
__device__ unsigned g_progress[NBLK];                       // monotonic counters

// ---------------------------------------------------------------------------
// Transpose (B,C,H,W) -> (W,B,H,C)
// ---------------------------------------------------------------------------
__global__ __launch_bounds__(256) void transpose_in_kernel(const float* __restrict__ states) {
    __shared__ float tile[32][33];
    const int wt = blockIdx.x, h = blockIdx.y, b = blockIdx.z;
    const int w0 = wt * 32;
    const int t  = threadIdx.x;
    const int lo = t & 31, g = t >> 5;
#pragma unroll
    for (int i = 0; i < 4; ++i) {
        int cc = g * 4 + i;
        tile[cc][lo] = states[((size_t)(b * 32 + cc) * 512 + h) * 512 + (w0 + lo)];
    }
    __syncthreads();
#pragma unroll
    for (int i = 0; i < 4; ++i) {
        int ww = g * 4 + i;
        g_Xt[((size_t)((w0 + ww) * 8 + b) * 512 + h) * 32 + lo] = tile[lo][ww];
    }
}

// ---------------------------------------------------------------------------
// Transpose (W,B,H,C) -> (B,C,H,W)
// ---------------------------------------------------------------------------
__global__ __launch_bounds__(256) void transpose_out_kernel(float* __restrict__ out) {
    __shared__ float tile[32][33];
    const int wt = blockIdx.x, h = blockIdx.y, b = blockIdx.z;
    const int w0 = wt * 32;
    const int t  = threadIdx.x;
    const int lo = t & 31, g = t >> 5;
#pragma unroll
    for (int i = 0; i < 4; ++i) {
        int ww = g * 4 + i;
        tile[ww][lo] = g_Yt[((size_t)((w0 + ww) * 8 + b) * 512 + h) * 32 + lo];
    }
    __syncthreads();
#pragma unroll
    for (int i = 0; i < 4; ++i) {
        int cc = g * 4 + i;
        out[((size_t)(b * 32 + cc) * 512 + h) * 512 + (w0 + lo)] = tile[lo][cc];
    }
}

// ---------------------------------------------------------------------------
// Persistent scan kernel. 128 blocks, each owns 32 (b,h) rows for all 511
// steps; previous output column lives in smem; halo rows (+-1) come from
// neighbor blocks via g_Yt with per-block monotonic progress flags
// (graph-replay safe: base re-read each run, +512 increments per run).
//
// smem layout (floats):
//   sWih : 96 x 100 (pad, stride%32==4 -> conflict-free float4) = 9600
//   sWhh : 96 x 36  (pad)                                       = 3456
//   sHs  : 34 x 32  (prev output col + 2 halo rows)             = 1088
//   sCur : 32 x 32  (current input col)                         = 1024
// total 15168 floats = 60672 bytes (dynamic)
// ---------------------------------------------------------------------------
#define SM_WIH 0
#define SM_WHH (SM_WIH + 96 * 100)
#define SM_HS  (SM_WHH + 96 * 36)
#define SM_CUR (SM_HS + 34 * 32)
#define SM_FLOATS (SM_CUR + 32 * 32)

__global__ __launch_bounds__(NTHR, 1) void scan_kernel(
    const float* __restrict__ Wih, const float* __restrict__ bih,
    const float* __restrict__ Whh, const float* __restrict__ bhh)
{
    extern __shared__ float sm[];
    float* sWih = sm + SM_WIH;
    float* sWhh = sm + SM_WHH;
    float* sHs  = sm + SM_HS;
    float* sCur = sm + SM_CUR;
    __shared__ unsigned sBase;

    const int tid  = threadIdx.x;
    const int beta = blockIdx.x;
    const int b    = beta >> 4;
    const int tile = beta & 15;
    const int h0   = tile * 32;
    const int c    = tid & 31;        // channel
    const int rq   = tid >> 5;        // row quad (0..7): rows rq*4 .. rq*4+3

    if (tid == 0) sBase = atomicAdd(&g_progress[beta], 0u);

    for (int i = tid; i < 96 * 96; i += NTHR) sWih[(i / 96) * 100 + (i % 96)] = Wih[i];
    for (int i = tid; i < 96 * 32; i += NTHR) sWhh[(i / 32) * 36  + (i % 32)] = Whh[i];

    const float br0 = bih[c]      + bhh[c];
    const float bz0 = bih[32 + c] + bhh[32 + c];
    const float bni = bih[64 + c];
    const float bnh = bhh[64 + c];
    __syncthreads();

    // Publish column 0 = input column 0 (identity passthrough)
    for (int i = tid; i < 1024; i += NTHR) {
        int r = i >> 5, cc = i & 31;
        size_t gi = ((size_t)b * 512 + (h0 + r)) * 32 + cc;   // w = 0
        float v = g_Xt[gi];
        sHs[(1 + r) * 32 + cc] = v;
        g_Yt[gi] = v;
    }
    __threadfence();
    __syncthreads();
    if (tid == 0) atomicExch(&g_progress[beta], sBase + 1);

    for (int w = 1; w < W_DIM; ++w) {
        // Current input column, coalesced float4 (256 threads x 16B = 4 KB)
        {
            const float4* src = (const float4*)&g_Xt[((size_t)(w * 8 + b) * 512 + h0) * 32];
            ((float4*)sCur)[tid] = src[tid];
        }

        // Wait for +-1 neighbor blocks to have published column w-1
        if (tid < 2) {
            int  nb    = (tid == 0) ? beta - 1 : beta + 1;
            bool valid = (tid == 0) ? (tile > 0) : (tile < 15);
            if (valid) {
                unsigned tgt = sBase + (unsigned)w;
                while (atomicAdd(&g_progress[nb], 0u) < tgt) { }
            }
        }
        __syncthreads();

        // Halo rows (h0-1, h0+32) of previous output column; L2-only loads
        if (tid < 32) {
            float v = 0.0f;
            if (tile > 0)
                v = __ldcg(&g_Yt[((size_t)((w - 1) * 8 + b) * 512 + (h0 - 1)) * 32 + tid]);
            sHs[tid] = v;
        } else if (tid < 64) {
            int cc = tid - 32;
            float v = 0.0f;
            if (tile < 15)
                v = __ldcg(&g_Yt[((size_t)((w - 1) * 8 + b) * 512 + (h0 + 32)) * 32 + cc]);
            sHs[33 * 32 + cc] = v;
        }
        __syncthreads();

        // ---- compute: 4 rows x 1 channel per thread -----------------------
        float ar[4], az[4], ani[4], anh[4];
#pragma unroll
        for (int i = 0; i < 4; ++i) { ar[i] = br0; az[i] = bz0; ani[i] = bni; anh[i] = bnh; }

        // i-part: x(96, = prev rows h-1,h,h+1 contiguous in sHs) @ Wih^T
#pragma unroll 8
        for (int kq = 0; kq < 24; ++kq) {
            float4 wr = *(const float4*)&sWih[(c)      * 100 + kq * 4];
            float4 wz = *(const float4*)&sWih[(32 + c) * 100 + kq * 4];
            float4 wn = *(const float4*)&sWih[(64 + c) * 100 + kq * 4];
#pragma unroll
            for (int i = 0; i < 4; ++i) {
                float4 xv = *(const float4*)&sHs[(rq * 4 + i) * 32 + kq * 4];
                ar[i]  = fmaf(xv.x, wr.x, fmaf(xv.y, wr.y, fmaf(xv.z, wr.z, fmaf(xv.w, wr.w, ar[i]))));
                az[i]  = fmaf(xv.x, wz.x, fmaf(xv.y, wz.y, fmaf(xv.z, wz.z, fmaf(xv.w, wz.w, az[i]))));
                ani[i] = fmaf(xv.x, wn.x, fmaf(xv.y, wn.y, fmaf(xv.z, wn.z, fmaf(xv.w, wn.w, ani[i]))));
            }
        }
        // h-part: cur col (32) @ Whh^T
#pragma unroll
        for (int kq = 0; kq < 8; ++kq) {
            float4 wr = *(const float4*)&sWhh[(c)      * 36 + kq * 4];
            float4 wz = *(const float4*)&sWhh[(32 + c) * 36 + kq * 4];
            float4 wn = *(const float4*)&sWhh[(64 + c) * 36 + kq * 4];
#pragma unroll
            for (int i = 0; i < 4; ++i) {
                float4 hv = *(const float4*)&sCur[(rq * 4 + i) * 32 + kq * 4];
                ar[i]  = fmaf(hv.x, wr.x, fmaf(hv.y, wr.y, fmaf(hv.z, wr.z, fmaf(hv.w, wr.w, ar[i]))));
                az[i]  = fmaf(hv.x, wz.x, fmaf(hv.y, wz.y, fmaf(hv.z, wz.z, fmaf(hv.w, wz.w, az[i]))));
                anh[i] = fmaf(hv.x, wn.x, fmaf(hv.y, wn.y, fmaf(hv.z, wn.z, fmaf(hv.w, wn.w, anh[i]))));
            }
        }

        float outv[4];
#pragma unroll
        for (int i = 0; i < 4; ++i) {
            float rg = 1.0f / (1.0f + __expf(-ar[i]));
            float zg = 1.0f / (1.0f + __expf(-az[i]));
            float ng = tanhf(fmaf(rg, anh[i], ani[i]));
            float cv = sCur[(rq * 4 + i) * 32 + c];
            outv[i]  = fmaf(ng - cv, zg, cv);   // n*z + cur*(1-z)
        }

        __syncthreads();   // all reads of sHs done before overwrite
#pragma unroll
        for (int i = 0; i < 4; ++i) {
            int r = rq * 4 + i;
            sHs[(1 + r) * 32 + c] = outv[i];
            g_Yt[((size_t)(w * 8 + b) * 512 + (h0 + r)) * 32 + c] = outv[i];
        }
        __threadfence();
        __syncthreads();
        if (tid == 0) atomicExch(&g_progress[beta], sBase + (unsigned)(w + 1));
    }
}

// ---------------------------------------------------------------------------
extern "C" void kernel_launch(void* const* d_in, const int* in_sizes, int n_in,
                              void* d_out, int out_size) {
    const float* states = (const float*)d_in[0];
    const float* wih    = (const float*)d_in[1];
    const float* bih    = (const float*)d_in[2];
    const float* whh    = (const float*)d_in[3];
    const float* bhh    = (const float*)d_in[4];
    float* out = (float*)d_out;

    cudaFuncSetAttribute(scan_kernel, cudaFuncAttributeMaxDynamicSharedMemorySize,
                         SM_FLOATS * (int)sizeof(float));

    dim3 tgrid(W_DIM / 32, H_DIM, B_DIM);
    transpose_in_kernel<<<tgrid, 256>>>(states);
    scan_kernel<<<NBLK, NTHR, SM_FLOATS * sizeof(float)>>>(wih, bih, whh, bhh);
    transpose_out_kernel<<<tgrid, 256>>>(out);
}